// round 1
// baseline (speedup 1.0000x reference)
#include <cuda_runtime.h>
#include <math.h>

#define T_STEPS 1000
#define BATCH   256
#define IDIM    128
#define NDIM    512
#define ALPHA   0.2f
#define NB      128    // persistent scan blocks (16 n-tiles x 8 b-tiles)

// ---------------------------------------------------------------------------
// Grid barrier state (persistent __device__ globals; zero-initialized once).
// Epoch is derived from the flags themselves at kernel start, so the barrier
// is correct across arbitrarily many graph replays.
// ---------------------------------------------------------------------------
__device__ unsigned g_flags[NB];

// ---------------------------------------------------------------------------
// Input projection GEMM:  C[M,N] = X[M,K] * W[N,K]^T + b
// M = T*B = 256000, K = 128, N = 512.  Tile 128x128, BK=16, 256 thr, 8x8 micro.
// ---------------------------------------------------------------------------
__global__ __launch_bounds__(256) void gemm_in_kernel(
    const float* __restrict__ X, const float* __restrict__ W,
    const float* __restrict__ bias, float* __restrict__ C)
{
    const int BK = 16;
    __shared__ float As[BK][128 + 4];
    __shared__ float Bs[BK][128 + 4];

    const int tid = threadIdx.x;
    const int tx = tid & 15;   // n group (8 cols each)
    const int ty = tid >> 4;   // m group (8 rows each)
    const int mBase = blockIdx.y * 128;
    const int nBase = blockIdx.x * 128;
    const float* Xblk = X + (size_t)mBase * IDIM;
    const float* Wblk = W + (size_t)nBase * IDIM;

    float acc[8][8];
#pragma unroll
    for (int i = 0; i < 8; i++)
#pragma unroll
        for (int j = 0; j < 8; j++) acc[i][j] = 0.f;

    for (int kc = 0; kc < IDIM; kc += BK) {
#pragma unroll
        for (int r = 0; r < 2; r++) {
            int f = tid + r * 256;          // [0,512) float4 slots
            int m = f >> 2;                 // row within tile
            int q = f & 3;                  // which float4 of the 16-wide k chunk
            float4 va = *(const float4*)(Xblk + (size_t)m * IDIM + kc + q * 4);
            As[q * 4 + 0][m] = va.x; As[q * 4 + 1][m] = va.y;
            As[q * 4 + 2][m] = va.z; As[q * 4 + 3][m] = va.w;
            float4 vb = *(const float4*)(Wblk + (size_t)m * IDIM + kc + q * 4);
            Bs[q * 4 + 0][m] = vb.x; Bs[q * 4 + 1][m] = vb.y;
            Bs[q * 4 + 2][m] = vb.z; Bs[q * 4 + 3][m] = vb.w;
        }
        __syncthreads();
#pragma unroll
        for (int k = 0; k < BK; k++) {
            float a[8], b[8];
            *(float4*)&a[0] = *(const float4*)&As[k][ty * 8];
            *(float4*)&a[4] = *(const float4*)&As[k][ty * 8 + 4];
            *(float4*)&b[0] = *(const float4*)&Bs[k][tx * 8];
            *(float4*)&b[4] = *(const float4*)&Bs[k][tx * 8 + 4];
#pragma unroll
            for (int i = 0; i < 8; i++)
#pragma unroll
                for (int j = 0; j < 8; j++)
                    acc[i][j] = fmaf(a[i], b[j], acc[i][j]);
        }
        __syncthreads();
    }

#pragma unroll
    for (int i = 0; i < 8; i++) {
        int m = mBase + ty * 8 + i;
        float* crow = C + (size_t)m * NDIM + nBase + tx * 8;
#pragma unroll
        for (int j = 0; j < 8; j++)
            crow[j] = acc[i][j] + bias[nBase + tx * 8 + j];
    }
}

// ---------------------------------------------------------------------------
// Persistent recurrent scan kernel.
//   out = [T][B][N] pre-filled with xproj; step t overwrites slice t with h_t.
//   128 blocks (16 n-tiles x 8 b-tiles), 64 threads, W_hh slice resident in
//   shared memory for all 1000 steps. 32x32 tile, 4x4 micro, k-vectorized.
// ---------------------------------------------------------------------------
__device__ __forceinline__ void load_hprev_tile(float4 v[4], const float* hprev,
                                                int bBase, int kc, int tid)
{
#pragma unroll
    for (int r = 0; r < 4; r++) {
        int f = tid + r * 64;   // [0,256) float4 slots
        int bl = f >> 3;        // local b row 0..31
        int q  = f & 7;         // float4 within 32-wide k chunk
        v[r] = __ldcg((const float4*)(hprev + (size_t)(bBase + bl) * NDIM + kc + q * 4));
    }
}

extern __shared__ float s_mem[];

__global__ __launch_bounds__(64) void ctrnn_scan_kernel(
    const float* __restrict__ h0,
    const float* __restrict__ W_hh,
    float* __restrict__ out)
{
    // shared partition: Wl[512][32] (64KB) then As[32][32] (4KB)
    float (*Wl)[32] = (float (*)[32])s_mem;
    float (*As)[32] = (float (*)[32])(s_mem + NDIM * 32);

    const int tid = threadIdx.x;
    const int tx = tid & 7;    // n group (4 each)
    const int ty = tid >> 3;   // b group (4 each)
    const int ni = blockIdx.x; // 0..15
    const int bi = blockIdx.y; // 0..7
    const int bid = bi * 16 + ni;
    const int nBase = ni * 32;
    const int bBase = bi * 32;

    // Load W_hh[nBase..nBase+32][0..512) transposed into Wl[k][n_local]. Once.
    {
        const float* Wb = W_hh + (size_t)nBase * NDIM;
        for (int f = tid; f < 32 * (NDIM / 4); f += 64) {
            int n = f >> 7;          // local n row
            int q = f & 127;         // float4 along k
            float4 v = *(const float4*)(Wb + (size_t)n * NDIM + q * 4);
            Wl[q * 4 + 0][n] = v.x; Wl[q * 4 + 1][n] = v.y;
            Wl[q * 4 + 2][n] = v.z; Wl[q * 4 + 3][n] = v.w;
        }
    }

    // Replay-safe epoch base: all flags are equal at kernel entry.
    unsigned base = ((volatile unsigned*)g_flags)[bid];
    __syncthreads();

    for (int t = 0; t < T_STEPS; t++) {
        const float* hprev = (t == 0) ? h0 : out + (size_t)(t - 1) * BATCH * NDIM;
        float* hcur = out + (size_t)t * BATCH * NDIM;

        // Prefetch epilogue operands (xproj slice t is always valid; hprev own
        // tile was written by THIS block last step, so valid after barrier).
        float4 xp4[4], hp4[4];
#pragma unroll
        for (int i = 0; i < 4; i++) {
            int b = bBase + ty * 4 + i;
            xp4[i] = *(const float4*)(hcur + (size_t)b * NDIM + nBase + tx * 4);
            hp4[i] = __ldcg((const float4*)(hprev + (size_t)b * NDIM + nBase + tx * 4));
        }

        float acc[4][4];
#pragma unroll
        for (int i = 0; i < 4; i++)
#pragma unroll
            for (int j = 0; j < 4; j++) acc[i][j] = 0.f;

        float4 v[4];
        load_hprev_tile(v, hprev, bBase, 0, tid);

        for (int kc = 0; kc < NDIM; kc += 32) {
            __syncthreads();   // previous chunk's As reads done
#pragma unroll
            for (int r = 0; r < 4; r++) {
                int f = tid + r * 64;
                int bl = f >> 3;
                int q  = f & 7;
                As[q * 4 + 0][bl] = v[r].x; As[q * 4 + 1][bl] = v[r].y;
                As[q * 4 + 2][bl] = v[r].z; As[q * 4 + 3][bl] = v[r].w;
            }
            __syncthreads();
            if (kc + 32 < NDIM) load_hprev_tile(v, hprev, bBase, kc + 32, tid);
#pragma unroll
            for (int k = 0; k < 32; k++) {
                float a[4], w[4];
                *(float4*)a = *(const float4*)&As[k][ty * 4];
                *(float4*)w = *(const float4*)&Wl[kc + k][tx * 4];
#pragma unroll
                for (int i = 0; i < 4; i++)
#pragma unroll
                    for (int j = 0; j < 4; j++)
                        acc[i][j] = fmaf(a[i], w[j], acc[i][j]);
            }
        }

        // Epilogue: h = 0.8*h_prev + 0.2*tanh(xp + h_prev @ W^T)
#pragma unroll
        for (int i = 0; i < 4; i++) {
            int b = bBase + ty * 4 + i;
            float4 o;
            o.x = hp4[i].x * (1.f - ALPHA) + ALPHA * tanhf(xp4[i].x + acc[i][0]);
            o.y = hp4[i].y * (1.f - ALPHA) + ALPHA * tanhf(xp4[i].y + acc[i][1]);
            o.z = hp4[i].z * (1.f - ALPHA) + ALPHA * tanhf(xp4[i].z + acc[i][2]);
            o.w = hp4[i].w * (1.f - ALPHA) + ALPHA * tanhf(xp4[i].w + acc[i][3]);
            *(float4*)(hcur + (size_t)b * NDIM + nBase + tx * 4) = o;
        }

        // ---- grid barrier (flag array, release/acquire via threadfence) ----
        unsigned epoch = base + (unsigned)t + 1u;
        __syncthreads();
        __threadfence();
        if (tid == 0) ((volatile unsigned*)g_flags)[bid] = epoch;
        {
            volatile unsigned* vf = (volatile unsigned*)g_flags;
            while (vf[tid] < epoch) {}
            while (vf[tid + 64] < epoch) {}
        }
        __threadfence();
        __syncthreads();
    }
}

// ---------------------------------------------------------------------------
extern "C" void kernel_launch(void* const* d_in, const int* in_sizes, int n_in,
                              void* d_out, int out_size)
{
    (void)in_sizes; (void)n_in; (void)out_size;
    const float* x    = (const float*)d_in[0];  // [T,B,I]
    const float* h0   = (const float*)d_in[1];  // [B,N]
    const float* W_in = (const float*)d_in[2];  // [N,I]
    const float* b_in = (const float*)d_in[3];  // [N]
    const float* W_hh = (const float*)d_in[4];  // [N,N]
    float* out = (float*)d_out;                 // [T,B,N] then [B,N]

    // 1) xproj = x @ W_in^T + b_in  -> written straight into out[0 : T*B*N]
    {
        dim3 grid(NDIM / 128, (T_STEPS * BATCH) / 128);
        gemm_in_kernel<<<grid, 256>>>(x, W_in, b_in, out);
    }

    // 2) persistent scan over 1000 steps (in-place on out slices)
    {
        size_t smem = (size_t)(NDIM * 32 + 32 * 32) * sizeof(float); // 68 KB
        cudaFuncSetAttribute(ctrnn_scan_kernel,
                             cudaFuncAttributeMaxDynamicSharedMemorySize,
                             (int)smem);
        dim3 grid(16, 8);  // 128 blocks, guaranteed co-resident on 148 SMs
        ctrnn_scan_kernel<<<grid, 64, smem>>>(h0, W_hh, out);
    }

    // 3) hidden = out[T-1] duplicated after the output block
    {
        size_t slice = (size_t)BATCH * NDIM * sizeof(float);
        cudaMemcpyAsync((char*)d_out + (size_t)T_STEPS * BATCH * NDIM * sizeof(float),
                        (char*)d_out + (size_t)(T_STEPS - 1) * BATCH * NDIM * sizeof(float),
                        slice, cudaMemcpyDeviceToDevice, 0);
    }
}

// round 2
// speedup vs baseline: 1.4439x; 1.4439x over previous
#include <cuda_runtime.h>
#include <math.h>

#define T_STEPS 1000
#define BATCH   256
#define IDIM    128
#define NDIM    512
#define ALPHA   0.2f
#define NB      128    // persistent scan blocks (16 n-tiles x 8 b-tiles)

#define HS_STRIDE 132  // 128 k-floats per row + 4 pad (conflict-free)
#define RED_STRIDE 36  // 32 + 4 pad, 16B-aligned rows

// Shared memory layout (floats):
//   Wl  [512][32]            @ 0        (64 KB)  W_hh slice, resident all steps
//   Hs  [4][32][HS_STRIDE]   @ 16384    (66 KB)  per-group staged hprev tile
//   red [4][32][RED_STRIDE]  @ 33280    (18 KB)  per-group partial sums
#define SMEM_WL   0
#define SMEM_HS   16384
#define SMEM_RED  33280
#define SMEM_FLOATS (SMEM_RED + 4 * 32 * RED_STRIDE)

// ---------------------------------------------------------------------------
// Grid barrier flags (persistent; epoch derived from flag state => replay-safe)
// ---------------------------------------------------------------------------
__device__ unsigned g_flags[NB];

// ---------------------------------------------------------------------------
// Input projection GEMM:  C[M,N] = X[M,K] * W[N,K]^T + b
// M = T*B = 256000, K = 128, N = 512.  Tile 128x128, BK=16, 256 thr, 8x8 micro.
// ---------------------------------------------------------------------------
__global__ __launch_bounds__(256) void gemm_in_kernel(
    const float* __restrict__ X, const float* __restrict__ W,
    const float* __restrict__ bias, float* __restrict__ C)
{
    const int BK = 16;
    __shared__ float As[BK][128 + 4];
    __shared__ float Bs[BK][128 + 4];

    const int tid = threadIdx.x;
    const int tx = tid & 15;   // n group (8 cols each)
    const int ty = tid >> 4;   // m group (8 rows each)
    const int mBase = blockIdx.y * 128;
    const int nBase = blockIdx.x * 128;
    const float* Xblk = X + (size_t)mBase * IDIM;
    const float* Wblk = W + (size_t)nBase * IDIM;

    float acc[8][8];
#pragma unroll
    for (int i = 0; i < 8; i++)
#pragma unroll
        for (int j = 0; j < 8; j++) acc[i][j] = 0.f;

    for (int kc = 0; kc < IDIM; kc += BK) {
#pragma unroll
        for (int r = 0; r < 2; r++) {
            int f = tid + r * 256;          // [0,512) float4 slots
            int m = f >> 2;                 // row within tile
            int q = f & 3;                  // which float4 of the 16-wide k chunk
            float4 va = *(const float4*)(Xblk + (size_t)m * IDIM + kc + q * 4);
            As[q * 4 + 0][m] = va.x; As[q * 4 + 1][m] = va.y;
            As[q * 4 + 2][m] = va.z; As[q * 4 + 3][m] = va.w;
            float4 vb = *(const float4*)(Wblk + (size_t)m * IDIM + kc + q * 4);
            Bs[q * 4 + 0][m] = vb.x; Bs[q * 4 + 1][m] = vb.y;
            Bs[q * 4 + 2][m] = vb.z; Bs[q * 4 + 3][m] = vb.w;
        }
        __syncthreads();
#pragma unroll
        for (int k = 0; k < BK; k++) {
            float a[8], b[8];
            *(float4*)&a[0] = *(const float4*)&As[k][ty * 8];
            *(float4*)&a[4] = *(const float4*)&As[k][ty * 8 + 4];
            *(float4*)&b[0] = *(const float4*)&Bs[k][tx * 8];
            *(float4*)&b[4] = *(const float4*)&Bs[k][tx * 8 + 4];
#pragma unroll
            for (int i = 0; i < 8; i++)
#pragma unroll
                for (int j = 0; j < 8; j++)
                    acc[i][j] = fmaf(a[i], b[j], acc[i][j]);
        }
        __syncthreads();
    }

#pragma unroll
    for (int i = 0; i < 8; i++) {
        int m = mBase + ty * 8 + i;
        float* crow = C + (size_t)m * NDIM + nBase + tx * 8;
#pragma unroll
        for (int j = 0; j < 8; j++)
            crow[j] = acc[i][j] + bias[nBase + tx * 8 + j];
    }
}

// ---------------------------------------------------------------------------
// Persistent recurrent scan kernel. 128 blocks x 256 threads.
//   Block (bi, ni): output tile rows [bi*32, +32) x cols [ni*32, +32).
//   256 threads = 4 k-groups of 64; group g covers k in [g*128, g*128+128).
//   W_hh slice [32 n x 512 k] resident in smem for all 1000 steps.
//   Grid barrier scoped to the 16 blocks sharing bi (only they produce the
//   hprev rows this block consumes).
// ---------------------------------------------------------------------------
extern __shared__ float s_mem[];

__global__ __launch_bounds__(256, 1) void ctrnn_scan_kernel(
    const float* __restrict__ h0,
    const float* __restrict__ W_hh,
    float* __restrict__ out)
{
    float* Wl = s_mem + SMEM_WL;

    const int tid = threadIdx.x;
    const int g    = tid >> 6;      // k-group 0..3
    const int gtid = tid & 63;
    const int tx = gtid & 7;        // n micro (4 cols)
    const int ty = gtid >> 3;       // b micro (4 rows)
    const int kOff = g << 7;        // group k offset

    const int ni = blockIdx.x;      // 0..15
    const int bi = blockIdx.y;      // 0..7
    const int bid = bi * 16 + ni;
    const int nBase = ni * 32;
    const int bBase = bi * 32;

    float* HsG  = s_mem + SMEM_HS  + g * (32 * HS_STRIDE);
    float* redG = s_mem + SMEM_RED + g * (32 * RED_STRIDE);

    // epilogue mapping: thread -> one float4 of the 32x32 output tile
    const int eb = tid >> 3;        // 0..31 local b row
    const int en = tid & 7;         // float4 col

    // Load W_hh[nBase..+32)[0..512) transposed into Wl[k][n_local]. Once.
    for (int f = tid; f < 32 * (NDIM / 4); f += 256) {
        int n = f >> 7;          // local n row
        int q = f & 127;         // float4 along k
        float4 v = *(const float4*)(W_hh + (size_t)(nBase + n) * NDIM + q * 4);
        Wl[(q * 4 + 0) * 32 + n] = v.x; Wl[(q * 4 + 1) * 32 + n] = v.y;
        Wl[(q * 4 + 2) * 32 + n] = v.z; Wl[(q * 4 + 3) * 32 + n] = v.w;
    }

    // Replay-safe epoch base: all flags equal at kernel entry.
    unsigned base = ((volatile unsigned*)g_flags)[bid];
    __syncthreads();

    for (int t = 0; t < T_STEPS; t++) {
        const float* hprev = (t == 0) ? h0 : out + (size_t)(t - 1) * BATCH * NDIM;
        float* hcur = out + (size_t)t * BATCH * NDIM;

        // Prefetch epilogue operands early (both valid after previous barrier).
        const size_t eoff = (size_t)(bBase + eb) * NDIM + nBase + en * 4;
        float4 xp4 = *(const float4*)(hcur + eoff);
        float4 hp4 = __ldcg((const float4*)(hprev + eoff));

        // Stage this group's k-quarter of the hprev b-tile: Hs[b][k] row-major.
#pragma unroll
        for (int r = 0; r < 16; r++) {
            int f = gtid + r * 64;
            int kq = f & 31;         // float4 within 128-wide quarter
            int bl = f >> 5;         // local b row
            float4 v = __ldcg((const float4*)(hprev +
                          (size_t)(bBase + bl) * NDIM + kOff + kq * 4));
            *(float4*)(HsG + bl * HS_STRIDE + kq * 4) = v;
        }
        asm volatile("bar.sync %0, 64;" :: "r"(1 + g) : "memory");

        float acc[4][4];
#pragma unroll
        for (int i = 0; i < 4; i++)
#pragma unroll
            for (int j = 0; j < 4; j++) acc[i][j] = 0.f;

        const float* a0p = HsG + (4 * ty + 0) * HS_STRIDE;
        const float* a1p = HsG + (4 * ty + 1) * HS_STRIDE;
        const float* a2p = HsG + (4 * ty + 2) * HS_STRIDE;
        const float* a3p = HsG + (4 * ty + 3) * HS_STRIDE;
        const float* wp  = Wl + (size_t)kOff * 32 + tx * 4;

#pragma unroll 8
        for (int k = 0; k < 128; k++) {
            float a0 = a0p[k], a1 = a1p[k], a2 = a2p[k], a3 = a3p[k];
            float4 w = *(const float4*)(wp + k * 32);
            acc[0][0] = fmaf(a0, w.x, acc[0][0]);
            acc[0][1] = fmaf(a0, w.y, acc[0][1]);
            acc[0][2] = fmaf(a0, w.z, acc[0][2]);
            acc[0][3] = fmaf(a0, w.w, acc[0][3]);
            acc[1][0] = fmaf(a1, w.x, acc[1][0]);
            acc[1][1] = fmaf(a1, w.y, acc[1][1]);
            acc[1][2] = fmaf(a1, w.z, acc[1][2]);
            acc[1][3] = fmaf(a1, w.w, acc[1][3]);
            acc[2][0] = fmaf(a2, w.x, acc[2][0]);
            acc[2][1] = fmaf(a2, w.y, acc[2][1]);
            acc[2][2] = fmaf(a2, w.z, acc[2][2]);
            acc[2][3] = fmaf(a2, w.w, acc[2][3]);
            acc[3][0] = fmaf(a3, w.x, acc[3][0]);
            acc[3][1] = fmaf(a3, w.y, acc[3][1]);
            acc[3][2] = fmaf(a3, w.z, acc[3][2]);
            acc[3][3] = fmaf(a3, w.w, acc[3][3]);
        }

        // Write partials; reduce + epilogue with all 256 threads.
#pragma unroll
        for (int i = 0; i < 4; i++) {
            float4 v = make_float4(acc[i][0], acc[i][1], acc[i][2], acc[i][3]);
            *(float4*)(redG + (4 * ty + i) * RED_STRIDE + tx * 4) = v;
        }
        __syncthreads();

        float4 s = make_float4(0.f, 0.f, 0.f, 0.f);
#pragma unroll
        for (int gg = 0; gg < 4; gg++) {
            float4 p = *(const float4*)(s_mem + SMEM_RED + gg * (32 * RED_STRIDE)
                                        + eb * RED_STRIDE + en * 4);
            s.x += p.x; s.y += p.y; s.z += p.z; s.w += p.w;
        }
        float4 o;
        o.x = hp4.x * (1.f - ALPHA) + ALPHA * tanhf(xp4.x + s.x);
        o.y = hp4.y * (1.f - ALPHA) + ALPHA * tanhf(xp4.y + s.y);
        o.z = hp4.z * (1.f - ALPHA) + ALPHA * tanhf(xp4.z + s.z);
        o.w = hp4.w * (1.f - ALPHA) + ALPHA * tanhf(xp4.w + s.w);
        *(float4*)(hcur + eoff) = o;

        // ---- barrier among the 16 blocks sharing bi ----
        unsigned epoch = base + (unsigned)t + 1u;
        __threadfence();
        __syncthreads();
        if (tid == 0) ((volatile unsigned*)g_flags)[bid] = epoch;
        if (tid < 16) {
            volatile unsigned* vf = (volatile unsigned*)g_flags + bi * 16;
            while (vf[tid] < epoch) {}
        }
        __threadfence();
        __syncthreads();
    }
}

// ---------------------------------------------------------------------------
extern "C" void kernel_launch(void* const* d_in, const int* in_sizes, int n_in,
                              void* d_out, int out_size)
{
    (void)in_sizes; (void)n_in; (void)out_size;
    const float* x    = (const float*)d_in[0];  // [T,B,I]
    const float* h0   = (const float*)d_in[1];  // [B,N]
    const float* W_in = (const float*)d_in[2];  // [N,I]
    const float* b_in = (const float*)d_in[3];  // [N]
    const float* W_hh = (const float*)d_in[4];  // [N,N]
    float* out = (float*)d_out;                 // [T,B,N] then [B,N]

    // 1) xproj = x @ W_in^T + b_in  -> written straight into out[0 : T*B*N]
    {
        dim3 grid(NDIM / 128, (T_STEPS * BATCH) / 128);
        gemm_in_kernel<<<grid, 256>>>(x, W_in, b_in, out);
    }

    // 2) persistent scan over 1000 steps (in-place on out slices)
    {
        size_t smem = (size_t)SMEM_FLOATS * sizeof(float); // ~148 KB
        cudaFuncSetAttribute(ctrnn_scan_kernel,
                             cudaFuncAttributeMaxDynamicSharedMemorySize,
                             (int)smem);
        dim3 grid(16, 8);  // 128 blocks, co-resident on 148 SMs
        ctrnn_scan_kernel<<<grid, 256, smem>>>(h0, W_hh, out);
    }

    // 3) hidden = out[T-1] duplicated after the output block
    {
        size_t slice = (size_t)BATCH * NDIM * sizeof(float);
        cudaMemcpyAsync((char*)d_out + (size_t)T_STEPS * BATCH * NDIM * sizeof(float),
                        (char*)d_out + (size_t)(T_STEPS - 1) * BATCH * NDIM * sizeof(float),
                        slice, cudaMemcpyDeviceToDevice, 0);
    }
}